// round 1
// baseline (speedup 1.0000x reference)
#include <cuda_runtime.h>
#include <math.h>

// Problem constants
#define B_ 2
#define S_ 1024
#define D_ 512
#define G_ 8
#define H_ 8
#define QKD_ 64
#define VD_ 64
#define GH_ (G_*H_)          // 64
#define QCOLS (GH_*QKD_)     // 4096
#define KVCOLS (G_*(QKD_+VD_)) // 1024
#define M_ (B_*S_)           // 2048

// Scratch (no device allocation allowed -> __device__ globals)
__device__ float g_q[M_ * QCOLS];    // [2048, 4096]
__device__ float g_kv[M_ * KVCOLS];  // [2048, 1024]
__device__ float g_z[M_ * QCOLS];    // [2048, 4096]

// ---------------------------------------------------------------------------
// Tiled fp32 GEMM body: C[M,N] = A[M,K] @ W[K,N] + bias, optional leaky ReLU.
// BM=BN=64, BK=16, 256 threads, 4x4 per thread. All dims divisible.
// ---------------------------------------------------------------------------
__device__ __forceinline__ void gemm_body(const float* __restrict__ A,
                                          const float* __restrict__ W,
                                          const float* __restrict__ bias,
                                          float* __restrict__ C,
                                          int M, int N, int K, bool leaky) {
    __shared__ float As[64][17];   // padded vs bank conflicts
    __shared__ float Ws[16][64];

    const int n0 = blockIdx.x * 64;
    const int m0 = blockIdx.y * 64;
    const int tid = threadIdx.x;
    const int tx = tid & 15;       // 0..15 -> 4 cols each
    const int ty = tid >> 4;       // 0..15 -> 4 rows each

    float acc[4][4];
#pragma unroll
    for (int i = 0; i < 4; i++)
#pragma unroll
        for (int j = 0; j < 4; j++) acc[i][j] = 0.f;

    for (int k0 = 0; k0 < K; k0 += 16) {
        // Load A tile: 64x16 = 1024 floats, 256 threads -> one float4 each
        {
            int r = tid >> 2;
            int c = (tid & 3) << 2;
            float4 v = *reinterpret_cast<const float4*>(A + (size_t)(m0 + r) * K + k0 + c);
            As[r][c + 0] = v.x; As[r][c + 1] = v.y;
            As[r][c + 2] = v.z; As[r][c + 3] = v.w;
        }
        // Load W tile: 16x64 = 1024 floats -> one float4 each
        {
            int r = tid >> 4;
            int c = (tid & 15) << 2;
            float4 v = *reinterpret_cast<const float4*>(W + (size_t)(k0 + r) * N + n0 + c);
            *reinterpret_cast<float4*>(&Ws[r][c]) = v;
        }
        __syncthreads();

#pragma unroll
        for (int k = 0; k < 16; k++) {
            float a[4], b[4];
#pragma unroll
            for (int i = 0; i < 4; i++) a[i] = As[ty * 4 + i][k];
#pragma unroll
            for (int j = 0; j < 4; j++) b[j] = Ws[k][tx * 4 + j];
#pragma unroll
            for (int i = 0; i < 4; i++)
#pragma unroll
                for (int j = 0; j < 4; j++) acc[i][j] += a[i] * b[j];
        }
        __syncthreads();
    }

#pragma unroll
    for (int i = 0; i < 4; i++) {
        int row = m0 + ty * 4 + i;
#pragma unroll
        for (int j = 0; j < 4; j++) {
            int col = n0 + tx * 4 + j;
            float v = acc[i][j] + bias[col];
            if (leaky) v = (v > 0.f) ? v : 0.01f * v;
            C[(size_t)row * N + col] = v;
        }
    }
}

__global__ void k_proj_q(const float* __restrict__ x, const float* __restrict__ w,
                         const float* __restrict__ b) {
    gemm_body(x, w, b, g_q, M_, QCOLS, D_, false);
}
__global__ void k_proj_kv(const float* __restrict__ x, const float* __restrict__ w,
                          const float* __restrict__ b) {
    gemm_body(x, w, b, g_kv, M_, KVCOLS, D_, false);
}
__global__ void k_proj_out(const float* __restrict__ w, const float* __restrict__ b,
                           float* __restrict__ out) {
    gemm_body(g_z, w, b, out, M_, D_, QCOLS, true);
}

// ---------------------------------------------------------------------------
// Flash-style attention, fp32. One thread = one query row.
// grid = (S/128, B*G*H), block = 128 threads.
// q:  g_q [b*S+s][gh*64 + d]
// k:  g_kv[b*S+t][g*64 + d]          (first 512 cols)
// v:  g_kv[b*S+t][512 + g*64 + d]
// z:  g_z [b*S+s][gh*64 + d]
// ---------------------------------------------------------------------------
__global__ void __launch_bounds__(128) k_attn() {
    const int bgh = blockIdx.y;          // 0..127
    const int b = bgh >> 6;              // /64
    const int gh = bgh & 63;
    const int g = gh >> 3;
    const int s = blockIdx.x * 128 + threadIdx.x;

    const float scale = 0.125f;          // 1/sqrt(64)

    float Q[64];
    const float* qp = g_q + (size_t)(b * S_ + s) * QCOLS + gh * 64;
#pragma unroll
    for (int d = 0; d < 64; d += 4) {
        float4 t = *reinterpret_cast<const float4*>(qp + d);
        Q[d + 0] = t.x * scale; Q[d + 1] = t.y * scale;
        Q[d + 2] = t.z * scale; Q[d + 3] = t.w * scale;
    }

    float O[64];
#pragma unroll
    for (int d = 0; d < 64; d++) O[d] = 0.f;
    float m = -1e30f, l = 0.f;

    __shared__ float Ks[64][64];
    __shared__ float Vs[64][64];

    for (int t0 = 0; t0 < S_; t0 += 64) {
        __syncthreads();
        // cooperative load of K/V tiles: 64 rows x 16 float4 = 1024 float4 / 128 thr
        for (int i = threadIdx.x; i < 64 * 16; i += 128) {
            int r = i >> 4;
            int c = (i & 15) << 2;
            const float* kp = g_kv + (size_t)(b * S_ + t0 + r) * KVCOLS + g * 64 + c;
            *reinterpret_cast<float4*>(&Ks[r][c]) = *reinterpret_cast<const float4*>(kp);
            *reinterpret_cast<float4*>(&Vs[r][c]) = *reinterpret_cast<const float4*>(kp + G_ * QKD_);
        }
        __syncthreads();

#pragma unroll 4
        for (int j = 0; j < 64; j++) {
            float sc = 0.f;
#pragma unroll
            for (int d = 0; d < 64; d++) sc += Q[d] * Ks[j][d];

            if (sc > m) {
                float corr = __expf(m - sc);
                l *= corr;
#pragma unroll
                for (int d = 0; d < 64; d++) O[d] *= corr;
                m = sc;
            }
            float p = __expf(sc - m);
            l += p;
#pragma unroll
            for (int d = 0; d < 64; d++) O[d] += p * Vs[j][d];
        }
    }

    float inv = 1.f / l;
    float* zp = g_z + (size_t)(b * S_ + s) * QCOLS + gh * 64;
#pragma unroll
    for (int d = 0; d < 64; d += 4) {
        float4 t;
        t.x = O[d + 0] * inv; t.y = O[d + 1] * inv;
        t.z = O[d + 2] * inv; t.w = O[d + 3] * inv;
        *reinterpret_cast<float4*>(zp + d) = t;
    }
}

// ---------------------------------------------------------------------------
extern "C" void kernel_launch(void* const* d_in, const int* in_sizes, int n_in,
                              void* d_out, int out_size) {
    const float* x     = (const float*)d_in[0];
    const float* Wq_w  = (const float*)d_in[1];
    const float* Wq_b  = (const float*)d_in[2];
    const float* Wkv_w = (const float*)d_in[3];
    const float* Wkv_b = (const float*)d_in[4];
    const float* Wz_w  = (const float*)d_in[5];
    const float* Wz_b  = (const float*)d_in[6];
    float* out = (float*)d_out;

    dim3 gq(QCOLS / 64, M_ / 64);     // (64, 32)
    k_proj_q<<<gq, 256>>>(x, Wq_w, Wq_b);

    dim3 gkv(KVCOLS / 64, M_ / 64);   // (16, 32)
    k_proj_kv<<<gkv, 256>>>(x, Wkv_w, Wkv_b);

    dim3 ga(S_ / 128, B_ * G_ * H_);  // (8, 128)
    k_attn<<<ga, 128>>>();

    dim3 go(D_ / 64, M_ / 64);        // (8, 32)
    k_proj_out<<<go, 256>>>(Wz_w, Wz_b, out);
}

// round 2
// speedup vs baseline: 3.0635x; 3.0635x over previous
#include <cuda_runtime.h>
#include <cstdint>

#define B_ 2
#define S_ 1024
#define D_ 512
#define G_ 8
#define QKD_ 64
#define VD_ 64
#define GH_ 64
#define QCOLS 4096
#define KVCOLS 1024
#define M_ 2048

// Scratch (no device allocation allowed -> __device__ globals)
__device__ float g_q[M_ * QCOLS];    // [2048, 4096]
__device__ float g_kv[M_ * KVCOLS];  // [2048, 1024]
__device__ float g_z[M_ * QCOLS];    // [2048, 4096]

// ---------------------------------------------------------------------------
// Helpers: tf32 convert (round-to-nearest, unbiased) and m16n8k8 tf32 mma
// ---------------------------------------------------------------------------
__device__ __forceinline__ uint32_t f2tf(float f) {
    uint32_t u;
    asm("cvt.rna.tf32.f32 %0, %1;" : "=r"(u) : "f"(f));
    return u;
}

__device__ __forceinline__ void mma_tf32(float* d,
                                         uint32_t a0, uint32_t a1, uint32_t a2, uint32_t a3,
                                         uint32_t b0, uint32_t b1) {
    asm volatile(
        "mma.sync.aligned.m16n8k8.row.col.f32.tf32.tf32.f32 "
        "{%0,%1,%2,%3}, {%4,%5,%6,%7}, {%8,%9}, {%0,%1,%2,%3};"
        : "+f"(d[0]), "+f"(d[1]), "+f"(d[2]), "+f"(d[3])
        : "r"(a0), "r"(a1), "r"(a2), "r"(a3), "r"(b0), "r"(b1));
}

// exp(x) for x <= 0 via FMA-pipe exp2 polynomial (no MUFU).
__device__ __forceinline__ float fast_exp(float x) {
    float y = x * 1.4426950408889634f;
    y = fmaxf(y, -100.0f);
    float n = floorf(y);
    float f = y - n;
    float p = 0.000154035304f;
    p = fmaf(p, f, 0.00133335581f);
    p = fmaf(p, f, 0.00961812911f);
    p = fmaf(p, f, 0.0555041087f);
    p = fmaf(p, f, 0.240226507f);
    p = fmaf(p, f, 0.693147181f);
    p = fmaf(p, f, 1.0f);
    return p * __int_as_float(((int)n + 127) << 23);
}

// ---------------------------------------------------------------------------
// tf32 tensor-core GEMM: C[M,N] = A[M,K] @ W[K,N] + bias (+ optional leaky).
// BM=128, BN=64, BK=32, 256 threads = 8 warps (4 m-warps x 2 n-warps).
// Warp tile 32(m) x 32(n). Per thread: 2 m-frags x 4 n-frags x 4 accs.
// ---------------------------------------------------------------------------
__global__ void __launch_bounds__(256) gemm_tf32(
    const float* __restrict__ A, const float* __restrict__ W,
    const float* __restrict__ bias, float* __restrict__ C,
    int M, int N, int K, int leaky)
{
    __shared__ uint32_t As[128][36];  // pitch 36: bank = 4g+t -> conflict-free frags
    __shared__ uint32_t Ws[32][72];   // pitch 72: bank = 8t+g -> conflict-free frags

    const int n0 = blockIdx.x * 64;
    const int m0 = blockIdx.y * 128;
    const int tid = threadIdx.x;
    const int lane = tid & 31;
    const int wid = tid >> 5;
    const int lg = lane >> 2;   // group id 0..7
    const int lt = lane & 3;    // thread-in-group 0..3
    const int wm = wid & 3;     // m-warp 0..3
    const int wn = wid >> 2;    // n-warp 0..1

    float acc[2][4][4];
#pragma unroll
    for (int i = 0; i < 2; i++)
#pragma unroll
        for (int j = 0; j < 4; j++)
#pragma unroll
            for (int k = 0; k < 4; k++) acc[i][j][k] = 0.f;

    for (int k0 = 0; k0 < K; k0 += 32) {
        // Load A tile 128x32 (1024 float4, 4 per thread)
#pragma unroll
        for (int it = 0; it < 4; it++) {
            int lin = tid + it * 256;
            int r = lin >> 3;
            int c = (lin & 7) << 2;
            float4 v = *reinterpret_cast<const float4*>(A + (size_t)(m0 + r) * K + k0 + c);
            As[r][c + 0] = f2tf(v.x); As[r][c + 1] = f2tf(v.y);
            As[r][c + 2] = f2tf(v.z); As[r][c + 3] = f2tf(v.w);
        }
        // Load W tile 32x64 (512 float4, 2 per thread)
#pragma unroll
        for (int it = 0; it < 2; it++) {
            int lin = tid + it * 256;
            int r = lin >> 4;
            int c = (lin & 15) << 2;
            float4 v = *reinterpret_cast<const float4*>(W + (size_t)(k0 + r) * N + n0 + c);
            Ws[r][c + 0] = f2tf(v.x); Ws[r][c + 1] = f2tf(v.y);
            Ws[r][c + 2] = f2tf(v.z); Ws[r][c + 3] = f2tf(v.w);
        }
        __syncthreads();

#pragma unroll
        for (int kk = 0; kk < 4; kk++) {
            uint32_t af[2][4];
#pragma unroll
            for (int mf = 0; mf < 2; mf++) {
                int row = wm * 32 + mf * 16;
                af[mf][0] = As[row + lg][kk * 8 + lt];
                af[mf][1] = As[row + lg + 8][kk * 8 + lt];
                af[mf][2] = As[row + lg][kk * 8 + lt + 4];
                af[mf][3] = As[row + lg + 8][kk * 8 + lt + 4];
            }
#pragma unroll
            for (int nf = 0; nf < 4; nf++) {
                int col = wn * 32 + nf * 8 + lg;
                uint32_t b0 = Ws[kk * 8 + lt][col];
                uint32_t b1 = Ws[kk * 8 + lt + 4][col];
#pragma unroll
                for (int mf = 0; mf < 2; mf++)
                    mma_tf32(acc[mf][nf], af[mf][0], af[mf][1], af[mf][2], af[mf][3], b0, b1);
            }
        }
        __syncthreads();
    }

    // Epilogue
#pragma unroll
    for (int mf = 0; mf < 2; mf++) {
        int row = m0 + wm * 32 + mf * 16 + lg;
#pragma unroll
        for (int nf = 0; nf < 4; nf++) {
            int col = n0 + wn * 32 + nf * 8 + 2 * lt;
            float b0 = bias[col], b1 = bias[col + 1];
            float v0 = acc[mf][nf][0] + b0;
            float v1 = acc[mf][nf][1] + b1;
            float v2 = acc[mf][nf][2] + b0;
            float v3 = acc[mf][nf][3] + b1;
            if (leaky) {
                v0 = (v0 > 0.f) ? v0 : 0.01f * v0;
                v1 = (v1 > 0.f) ? v1 : 0.01f * v1;
                v2 = (v2 > 0.f) ? v2 : 0.01f * v2;
                v3 = (v3 > 0.f) ? v3 : 0.01f * v3;
            }
            float2 o0 = make_float2(v0, v1);
            float2 o1 = make_float2(v2, v3);
            *reinterpret_cast<float2*>(C + (size_t)row * N + col) = o0;
            *reinterpret_cast<float2*>(C + (size_t)(row + 8) * N + col) = o1;
        }
    }
}

// ---------------------------------------------------------------------------
// Flash attention with tf32 mma + FMA-poly softmax.
// Block: 1 head (b,gh), 128 query rows, 256 threads = 8 warps (16 rows each).
// Key loop: 16 tiles of 64 keys. Dyn smem: QP(128x68, Q then P), Ks(64x68),
// Vs(64x72) -- pitches give conflict-free mma-fragment LDS.
// ---------------------------------------------------------------------------
#define QP_PITCH 68
#define KS_PITCH 68
#define VS_PITCH 72
#define ATTN_SMEM_WORDS (128 * QP_PITCH + 64 * KS_PITCH + 64 * VS_PITCH)

__global__ void __launch_bounds__(256) attn_mma() {
    extern __shared__ uint32_t dsm[];
    uint32_t* QP = dsm;                       // 128 x 68
    uint32_t* Ks = QP + 128 * QP_PITCH;       // 64 x 68
    uint32_t* Vs = Ks + 64 * KS_PITCH;        // 64 x 72

    const int bgh = blockIdx.y;               // 0..127
    const int b = bgh >> 6;
    const int gh = bgh & 63;
    const int g = gh >> 3;
    const int q0 = blockIdx.x * 128;
    const int tid = threadIdx.x;
    const int lane = tid & 31;
    const int wid = tid >> 5;
    const int lg = lane >> 2;
    const int lt = lane & 3;
    const int rw = wid * 16;                  // warp's query-row base in tile

    // Load Q tile (pre-scaled by 1/sqrt(64)) into smem as tf32
    for (int i = tid; i < 128 * 16; i += 256) {
        int r = i >> 4;
        int c = (i & 15) << 2;
        float4 v = *reinterpret_cast<const float4*>(
            g_q + (size_t)(b * S_ + q0 + r) * QCOLS + gh * 64 + c);
        uint32_t* row = QP + r * QP_PITCH + c;
        row[0] = f2tf(v.x * 0.125f); row[1] = f2tf(v.y * 0.125f);
        row[2] = f2tf(v.z * 0.125f); row[3] = f2tf(v.w * 0.125f);
    }
    __syncthreads();

    // Q A-fragments for all 8 k-steps (held for whole kernel)
    uint32_t QA[8][4];
#pragma unroll
    for (int ks = 0; ks < 8; ks++) {
        QA[ks][0] = QP[(rw + lg) * QP_PITCH + 8 * ks + lt];
        QA[ks][1] = QP[(rw + lg + 8) * QP_PITCH + 8 * ks + lt];
        QA[ks][2] = QP[(rw + lg) * QP_PITCH + 8 * ks + lt + 4];
        QA[ks][3] = QP[(rw + lg + 8) * QP_PITCH + 8 * ks + lt + 4];
    }
    __syncthreads();   // QP now reused as P buffer (warp-private rows)

    float OC[8][4];
#pragma unroll
    for (int i = 0; i < 8; i++)
#pragma unroll
        for (int j = 0; j < 4; j++) OC[i][j] = 0.f;
    float m0 = -1e30f, m1 = -1e30f, l0 = 0.f, l1 = 0.f;

    for (int kb = 0; kb < 16; kb++) {
        // Load K/V tiles (64 keys x 64 d) as tf32
        for (int i = tid; i < 64 * 16; i += 256) {
            int r = i >> 4;
            int c = (i & 15) << 2;
            const float* kp = g_kv + (size_t)(b * S_ + kb * 64 + r) * KVCOLS + g * 64 + c;
            float4 kv4 = *reinterpret_cast<const float4*>(kp);
            float4 vv4 = *reinterpret_cast<const float4*>(kp + G_ * QKD_);
            uint32_t* krow = Ks + r * KS_PITCH + c;
            krow[0] = f2tf(kv4.x); krow[1] = f2tf(kv4.y);
            krow[2] = f2tf(kv4.z); krow[3] = f2tf(kv4.w);
            uint32_t* vrow = Vs + r * VS_PITCH + c;
            vrow[0] = f2tf(vv4.x); vrow[1] = f2tf(vv4.y);
            vrow[2] = f2tf(vv4.z); vrow[3] = f2tf(vv4.w);
        }
        __syncthreads();

        // S = Q @ K^T  (warp: 16 rows x 64 keys)
        float SC[8][4];
#pragma unroll
        for (int i = 0; i < 8; i++)
#pragma unroll
            for (int j = 0; j < 4; j++) SC[i][j] = 0.f;
#pragma unroll
        for (int nf = 0; nf < 8; nf++) {
#pragma unroll
            for (int ks = 0; ks < 8; ks++) {
                uint32_t b0 = Ks[(8 * nf + lg) * KS_PITCH + 8 * ks + lt];
                uint32_t b1 = Ks[(8 * nf + lg) * KS_PITCH + 8 * ks + lt + 4];
                mma_tf32(SC[nf], QA[ks][0], QA[ks][1], QA[ks][2], QA[ks][3], b0, b1);
            }
        }

        // Online softmax
        float mx0 = -1e30f, mx1 = -1e30f;
#pragma unroll
        for (int nf = 0; nf < 8; nf++) {
            mx0 = fmaxf(mx0, fmaxf(SC[nf][0], SC[nf][1]));
            mx1 = fmaxf(mx1, fmaxf(SC[nf][2], SC[nf][3]));
        }
        mx0 = fmaxf(mx0, __shfl_xor_sync(0xffffffffu, mx0, 1));
        mx0 = fmaxf(mx0, __shfl_xor_sync(0xffffffffu, mx0, 2));
        mx1 = fmaxf(mx1, __shfl_xor_sync(0xffffffffu, mx1, 1));
        mx1 = fmaxf(mx1, __shfl_xor_sync(0xffffffffu, mx1, 2));
        float nm0 = fmaxf(m0, mx0), nm1 = fmaxf(m1, mx1);
        float c0 = fast_exp(m0 - nm0), c1 = fast_exp(m1 - nm1);
        m0 = nm0; m1 = nm1;

        float rs0 = 0.f, rs1 = 0.f;
#pragma unroll
        for (int nf = 0; nf < 8; nf++) {
            float p00 = fast_exp(SC[nf][0] - m0);
            float p01 = fast_exp(SC[nf][1] - m0);
            float p10 = fast_exp(SC[nf][2] - m1);
            float p11 = fast_exp(SC[nf][3] - m1);
            rs0 += p00 + p01;
            rs1 += p10 + p11;
            QP[(rw + lg) * QP_PITCH + 8 * nf + 2 * lt]         = f2tf(p00);
            QP[(rw + lg) * QP_PITCH + 8 * nf + 2 * lt + 1]     = f2tf(p01);
            QP[(rw + lg + 8) * QP_PITCH + 8 * nf + 2 * lt]     = f2tf(p10);
            QP[(rw + lg + 8) * QP_PITCH + 8 * nf + 2 * lt + 1] = f2tf(p11);
        }
        rs0 += __shfl_xor_sync(0xffffffffu, rs0, 1);
        rs0 += __shfl_xor_sync(0xffffffffu, rs0, 2);
        rs1 += __shfl_xor_sync(0xffffffffu, rs1, 1);
        rs1 += __shfl_xor_sync(0xffffffffu, rs1, 2);
        l0 = l0 * c0 + rs0;
        l1 = l1 * c1 + rs1;
#pragma unroll
        for (int nf = 0; nf < 8; nf++) {
            OC[nf][0] *= c0; OC[nf][1] *= c0;
            OC[nf][2] *= c1; OC[nf][3] *= c1;
        }
        __syncwarp();   // P stores visible to warp's own fragment loads

        // O += P @ V
#pragma unroll
        for (int ks = 0; ks < 8; ks++) {
            uint32_t a0 = QP[(rw + lg) * QP_PITCH + 8 * ks + lt];
            uint32_t a1 = QP[(rw + lg + 8) * QP_PITCH + 8 * ks + lt];
            uint32_t a2 = QP[(rw + lg) * QP_PITCH + 8 * ks + lt + 4];
            uint32_t a3 = QP[(rw + lg + 8) * QP_PITCH + 8 * ks + lt + 4];
#pragma unroll
            for (int nf = 0; nf < 8; nf++) {
                uint32_t b0 = Vs[(8 * ks + lt) * VS_PITCH + 8 * nf + lg];
                uint32_t b1 = Vs[(8 * ks + lt + 4) * VS_PITCH + 8 * nf + lg];
                mma_tf32(OC[nf], a0, a1, a2, a3, b0, b1);
            }
        }
        __syncthreads();  // all warps done with Ks/Vs before next tile load
    }

    // Epilogue: normalize, write z
    float inv0 = 1.f / l0, inv1 = 1.f / l1;
    size_t row0 = (size_t)(b * S_ + q0 + rw + lg);
#pragma unroll
    for (int nf = 0; nf < 8; nf++) {
        int col = gh * 64 + nf * 8 + 2 * lt;
        float2 o0 = make_float2(OC[nf][0] * inv0, OC[nf][1] * inv0);
        float2 o1 = make_float2(OC[nf][2] * inv1, OC[nf][3] * inv1);
        *reinterpret_cast<float2*>(g_z + row0 * QCOLS + col) = o0;
        *reinterpret_cast<float2*>(g_z + (row0 + 8) * QCOLS + col) = o1;
    }
}

// ---------------------------------------------------------------------------
extern "C" void kernel_launch(void* const* d_in, const int* in_sizes, int n_in,
                              void* d_out, int out_size) {
    const float* x     = (const float*)d_in[0];
    const float* Wq_w  = (const float*)d_in[1];
    const float* Wq_b  = (const float*)d_in[2];
    const float* Wkv_w = (const float*)d_in[3];
    const float* Wkv_b = (const float*)d_in[4];
    const float* Wz_w  = (const float*)d_in[5];
    const float* Wz_b  = (const float*)d_in[6];
    float* out = (float*)d_out;

    static int attn_smem_set = 0;
    // idempotent attribute set (not an allocation; capture-safe)
    cudaFuncSetAttribute(attn_mma, cudaFuncAttributeMaxDynamicSharedMemorySize,
                         ATTN_SMEM_WORDS * 4);
    (void)attn_smem_set;

    float* gq;  cudaGetSymbolAddress((void**)&gq,  g_q);
    float* gkv; cudaGetSymbolAddress((void**)&gkv, g_kv);
    float* gz;  cudaGetSymbolAddress((void**)&gz,  g_z);

    dim3 gq_grid(QCOLS / 64, M_ / 128);      // (64, 16)
    gemm_tf32<<<gq_grid, 256>>>(x, Wq_w, Wq_b, gq, M_, QCOLS, D_, 0);

    dim3 gkv_grid(KVCOLS / 64, M_ / 128);    // (16, 16)
    gemm_tf32<<<gkv_grid, 256>>>(x, Wkv_w, Wkv_b, gkv, M_, KVCOLS, D_, 0);

    dim3 ga(S_ / 128, B_ * GH_);             // (8, 128)
    attn_mma<<<ga, 256, ATTN_SMEM_WORDS * 4>>>();

    dim3 go_grid(D_ / 64, M_ / 128);         // (8, 16)
    gemm_tf32<<<go_grid, 256>>>(gz, Wz_w, Wz_b, out, M_, D_, QCOLS, 1);
}

// round 6
// speedup vs baseline: 4.0143x; 1.3103x over previous
#include <cuda_runtime.h>
#include <cstdint>

#define B_ 2
#define S_ 1024
#define D_ 512
#define G_ 8
#define QKD_ 64
#define VD_ 64
#define GH_ 64
#define QCOLS 4096
#define KVCOLS 1024
#define M_ 2048
#define KSPLIT 4

// Scratch (no device allocation allowed -> __device__ globals)
__device__ float g_q[M_ * QCOLS];           // [2048, 4096]
__device__ float g_kv[M_ * KVCOLS];         // [2048, 1024]
__device__ float g_z[M_ * QCOLS];           // [2048, 4096]
__device__ float g_part[KSPLIT * M_ * D_];  // split-K partials, 16MB

// ---------------------------------------------------------------------------
__device__ __forceinline__ uint32_t f2tf(float f) {
    uint32_t u;
    asm("cvt.rna.tf32.f32 %0, %1;" : "=r"(u) : "f"(f));
    return u;
}

__device__ __forceinline__ void mma_tf32(float* d,
                                         uint32_t a0, uint32_t a1, uint32_t a2, uint32_t a3,
                                         uint32_t b0, uint32_t b1) {
    asm volatile(
        "mma.sync.aligned.m16n8k8.row.col.f32.tf32.tf32.f32 "
        "{%0,%1,%2,%3}, {%4,%5,%6,%7}, {%8,%9}, {%0,%1,%2,%3};"
        : "+f"(d[0]), "+f"(d[1]), "+f"(d[2]), "+f"(d[3])
        : "r"(a0), "r"(a1), "r"(a2), "r"(a3), "r"(b0), "r"(b1));
}

__device__ __forceinline__ void cp16(void* smem, const void* g) {
    uint32_t s = (uint32_t)__cvta_generic_to_shared(smem);
    asm volatile("cp.async.cg.shared.global [%0], [%1], 16;" :: "r"(s), "l"(g));
}
__device__ __forceinline__ void cp_commit() {
    asm volatile("cp.async.commit_group;");
}
template <int N>
__device__ __forceinline__ void cp_wait() {
    asm volatile("cp.async.wait_group %0;" :: "n"(N));
}

// exp(x) for x <= 0 via FMA-pipe exp2 polynomial (no MUFU).
__device__ __forceinline__ float fast_exp(float x) {
    float y = x * 1.4426950408889634f;
    y = fmaxf(y, -100.0f);
    float n = floorf(y);
    float f = y - n;
    float p = 0.000154035304f;
    p = fmaf(p, f, 0.00133335581f);
    p = fmaf(p, f, 0.00961812911f);
    p = fmaf(p, f, 0.0555041087f);
    p = fmaf(p, f, 0.240226507f);
    p = fmaf(p, f, 0.693147181f);
    p = fmaf(p, f, 1.0f);
    return p * __int_as_float(((int)n + 127) << 23);
}

// ---------------------------------------------------------------------------
// tf32 GEMM, register-prefetch double buffer.
// BM=128, BN=64, BK=32, 256 threads = 8 warps (4m x 2n), 32x32 warp tile.
// mode: 0 = bias, 1 = bias+leaky, 2 = raw partial (split-K, z-indexed).
// ---------------------------------------------------------------------------
__global__ void __launch_bounds__(256) gemm_tf32(
    const float* __restrict__ A, const float* __restrict__ W,
    const float* __restrict__ bias, float* __restrict__ C,
    int M, int N, int K, int kchunk, int mode)
{
    __shared__ uint32_t As[128][36];
    __shared__ uint32_t Ws[32][72];

    const int n0 = blockIdx.x * 64;
    const int m0 = blockIdx.y * 128;
    const int kbeg = blockIdx.z * kchunk;
    const int kend = kbeg + kchunk;
    const int tid = threadIdx.x;
    const int lane = tid & 31;
    const int wid = tid >> 5;
    const int lg = lane >> 2;
    const int lt = lane & 3;
    const int wm = wid & 3;
    const int wn = wid >> 2;

    // per-thread load coords
    int arr[4], arc[4];
#pragma unroll
    for (int it = 0; it < 4; it++) {
        int lin = tid + it * 256;
        arr[it] = lin >> 3;
        arc[it] = (lin & 7) << 2;
    }
    int wrr[2], wrc[2];
#pragma unroll
    for (int it = 0; it < 2; it++) {
        int lin = tid + it * 256;
        wrr[it] = lin >> 4;
        wrc[it] = (lin & 15) << 2;
    }

    float acc[2][4][4];
#pragma unroll
    for (int i = 0; i < 2; i++)
#pragma unroll
        for (int j = 0; j < 4; j++)
#pragma unroll
            for (int k = 0; k < 4; k++) acc[i][j][k] = 0.f;

    float4 ra[4], rw[2];
    // prologue load
#pragma unroll
    for (int it = 0; it < 4; it++)
        ra[it] = *reinterpret_cast<const float4*>(A + (size_t)(m0 + arr[it]) * K + kbeg + arc[it]);
#pragma unroll
    for (int it = 0; it < 2; it++)
        rw[it] = *reinterpret_cast<const float4*>(W + (size_t)(kbeg + wrr[it]) * N + n0 + wrc[it]);

    for (int k0 = kbeg; k0 < kend; k0 += 32) {
        // store current regs -> smem (rounded tf32)
#pragma unroll
        for (int it = 0; it < 4; it++) {
            uint32_t* row = &As[arr[it]][arc[it]];
            row[0] = f2tf(ra[it].x); row[1] = f2tf(ra[it].y);
            row[2] = f2tf(ra[it].z); row[3] = f2tf(ra[it].w);
        }
#pragma unroll
        for (int it = 0; it < 2; it++) {
            uint32_t* row = &Ws[wrr[it]][wrc[it]];
            row[0] = f2tf(rw[it].x); row[1] = f2tf(rw[it].y);
            row[2] = f2tf(rw[it].z); row[3] = f2tf(rw[it].w);
        }
        __syncthreads();

        // prefetch next tile into registers (overlaps with mma below)
        if (k0 + 32 < kend) {
#pragma unroll
            for (int it = 0; it < 4; it++)
                ra[it] = *reinterpret_cast<const float4*>(A + (size_t)(m0 + arr[it]) * K + k0 + 32 + arc[it]);
#pragma unroll
            for (int it = 0; it < 2; it++)
                rw[it] = *reinterpret_cast<const float4*>(W + (size_t)(k0 + 32 + wrr[it]) * N + n0 + wrc[it]);
        }

#pragma unroll
        for (int kk = 0; kk < 4; kk++) {
            uint32_t af[2][4];
#pragma unroll
            for (int mf = 0; mf < 2; mf++) {
                int row = wm * 32 + mf * 16;
                af[mf][0] = As[row + lg][kk * 8 + lt];
                af[mf][1] = As[row + lg + 8][kk * 8 + lt];
                af[mf][2] = As[row + lg][kk * 8 + lt + 4];
                af[mf][3] = As[row + lg + 8][kk * 8 + lt + 4];
            }
#pragma unroll
            for (int nf = 0; nf < 4; nf++) {
                int col = wn * 32 + nf * 8 + lg;
                uint32_t b0 = Ws[kk * 8 + lt][col];
                uint32_t b1 = Ws[kk * 8 + lt + 4][col];
#pragma unroll
                for (int mf = 0; mf < 2; mf++)
                    mma_tf32(acc[mf][nf], af[mf][0], af[mf][1], af[mf][2], af[mf][3], b0, b1);
            }
        }
        __syncthreads();
    }

    float* Cb = (mode == 2) ? (C + (size_t)blockIdx.z * M * N) : C;
#pragma unroll
    for (int mf = 0; mf < 2; mf++) {
        int row = m0 + wm * 32 + mf * 16 + lg;
#pragma unroll
        for (int nf = 0; nf < 4; nf++) {
            int col = n0 + wn * 32 + nf * 8 + 2 * lt;
            float v0 = acc[mf][nf][0], v1 = acc[mf][nf][1];
            float v2 = acc[mf][nf][2], v3 = acc[mf][nf][3];
            if (mode != 2) {
                float b0 = bias[col], b1 = bias[col + 1];
                v0 += b0; v1 += b1; v2 += b0; v3 += b1;
                if (mode == 1) {
                    v0 = (v0 > 0.f) ? v0 : 0.01f * v0;
                    v1 = (v1 > 0.f) ? v1 : 0.01f * v1;
                    v2 = (v2 > 0.f) ? v2 : 0.01f * v2;
                    v3 = (v3 > 0.f) ? v3 : 0.01f * v3;
                }
            }
            *reinterpret_cast<float2*>(Cb + (size_t)row * N + col) = make_float2(v0, v1);
            *reinterpret_cast<float2*>(Cb + (size_t)(row + 8) * N + col) = make_float2(v2, v3);
        }
    }
}

// Split-K reduce + bias + leaky ReLU for proj_out.
__global__ void __launch_bounds__(256) reduce_out(const float* __restrict__ bias,
                                                  float* __restrict__ out) {
    int i = blockIdx.x * 256 + threadIdx.x;           // float4 index over M*512
    const float4* p = reinterpret_cast<const float4*>(g_part);
    const int QW = M_ * D_ / 4;
    float4 a = p[i], b = p[i + QW], c = p[i + 2 * QW], d = p[i + 3 * QW];
    int col = (i & (D_ / 4 - 1)) * 4;
    float4 bb = *reinterpret_cast<const float4*>(bias + col);
    float v0 = a.x + b.x + c.x + d.x + bb.x;
    float v1 = a.y + b.y + c.y + d.y + bb.y;
    float v2 = a.z + b.z + c.z + d.z + bb.z;
    float v3 = a.w + b.w + c.w + d.w + bb.w;
    v0 = (v0 > 0.f) ? v0 : 0.01f * v0;
    v1 = (v1 > 0.f) ? v1 : 0.01f * v1;
    v2 = (v2 > 0.f) ? v2 : 0.01f * v2;
    v3 = (v3 > 0.f) ? v3 : 0.01f * v3;
    reinterpret_cast<float4*>(out)[i] = make_float4(v0, v1, v2, v3);
}

// ---------------------------------------------------------------------------
// Flash attention: tf32 mma, cp.async double-buffered K/V (raw fp32 in smem,
// hardware tf32 truncation on B operands), FMA-poly softmax.
// Block: 1 head (b,gh), 128 query rows, 256 threads = 8 warps (16 rows each).
// ---------------------------------------------------------------------------
#define QP_PITCH 68
#define KS_PITCH 68
#define VS_PITCH 72
#define KS_TILE (64 * KS_PITCH)
#define VS_TILE (64 * VS_PITCH)
#define ATTN_SMEM_WORDS (128 * QP_PITCH + 2 * KS_TILE + 2 * VS_TILE)

__global__ void __launch_bounds__(256) attn_mma() {
    extern __shared__ uint32_t dsm[];
    uint32_t* QP = dsm;                        // 128 x 68 (Q, then reused for P)
    uint32_t* Ks = QP + 128 * QP_PITCH;        // 2 x 64 x 68
    uint32_t* Vs = Ks + 2 * KS_TILE;           // 2 x 64 x 72

    const int bgh = blockIdx.y;
    const int b = bgh >> 6;
    const int gh = bgh & 63;
    const int g = gh >> 3;
    const int q0 = blockIdx.x * 128;
    const int tid = threadIdx.x;
    const int lane = tid & 31;
    const int wid = tid >> 5;
    const int lg = lane >> 2;
    const int lt = lane & 3;
    const int rw = wid * 16;

    // issue cp.async for one K/V tile into buffer `buf`
    auto issue_tile = [&](int kb, int buf) {
#pragma unroll
        for (int it = 0; it < 4; it++) {
            int i = tid + it * 256;
            int r = i >> 4;
            int c = (i & 15) << 2;
            const float* kp = g_kv + (size_t)(b * S_ + kb * 64 + r) * KVCOLS + g * 64 + c;
            cp16(Ks + buf * KS_TILE + r * KS_PITCH + c, kp);
            cp16(Vs + buf * VS_TILE + r * VS_PITCH + c, kp + G_ * QKD_);
        }
        cp_commit();
    };

    issue_tile(0, 0);   // prologue (overlaps with Q load below)

    // Load Q tile (pre-scaled) as rounded tf32
    for (int i = tid; i < 128 * 16; i += 256) {
        int r = i >> 4;
        int c = (i & 15) << 2;
        float4 v = *reinterpret_cast<const float4*>(
            g_q + (size_t)(b * S_ + q0 + r) * QCOLS + gh * 64 + c);
        uint32_t* row = QP + r * QP_PITCH + c;
        row[0] = f2tf(v.x * 0.125f); row[1] = f2tf(v.y * 0.125f);
        row[2] = f2tf(v.z * 0.125f); row[3] = f2tf(v.w * 0.125f);
    }
    __syncthreads();

    uint32_t QA[8][4];
#pragma unroll
    for (int ks = 0; ks < 8; ks++) {
        QA[ks][0] = QP[(rw + lg) * QP_PITCH + 8 * ks + lt];
        QA[ks][1] = QP[(rw + lg + 8) * QP_PITCH + 8 * ks + lt];
        QA[ks][2] = QP[(rw + lg) * QP_PITCH + 8 * ks + lt + 4];
        QA[ks][3] = QP[(rw + lg + 8) * QP_PITCH + 8 * ks + lt + 4];
    }
    __syncthreads();   // QP becomes P buffer

    float OC[8][4];
#pragma unroll
    for (int i = 0; i < 8; i++)
#pragma unroll
        for (int j = 0; j < 4; j++) OC[i][j] = 0.f;
    float m0 = -1e30f, m1 = -1e30f, l0 = 0.f, l1 = 0.f;

    for (int kb = 0; kb < 16; kb++) {
        const int buf = kb & 1;
        if (kb < 15) {
            issue_tile(kb + 1, buf ^ 1);
            cp_wait<1>();
        } else {
            cp_wait<0>();
        }
        __syncthreads();

        const uint32_t* Kb = Ks + buf * KS_TILE;
        const uint32_t* Vb = Vs + buf * VS_TILE;

        // S = Q @ K^T
        float SC[8][4];
#pragma unroll
        for (int i = 0; i < 8; i++)
#pragma unroll
            for (int j = 0; j < 4; j++) SC[i][j] = 0.f;
#pragma unroll
        for (int nf = 0; nf < 8; nf++) {
#pragma unroll
            for (int ks = 0; ks < 8; ks++) {
                uint32_t b0 = Kb[(8 * nf + lg) * KS_PITCH + 8 * ks + lt];
                uint32_t b1 = Kb[(8 * nf + lg) * KS_PITCH + 8 * ks + lt + 4];
                mma_tf32(SC[nf], QA[ks][0], QA[ks][1], QA[ks][2], QA[ks][3], b0, b1);
            }
        }

        // Online softmax
        float mx0 = -1e30f, mx1 = -1e30f;
#pragma unroll
        for (int nf = 0; nf < 8; nf++) {
            mx0 = fmaxf(mx0, fmaxf(SC[nf][0], SC[nf][1]));
            mx1 = fmaxf(mx1, fmaxf(SC[nf][2], SC[nf][3]));
        }
        mx0 = fmaxf(mx0, __shfl_xor_sync(0xffffffffu, mx0, 1));
        mx0 = fmaxf(mx0, __shfl_xor_sync(0xffffffffu, mx0, 2));
        mx1 = fmaxf(mx1, __shfl_xor_sync(0xffffffffu, mx1, 1));
        mx1 = fmaxf(mx1, __shfl_xor_sync(0xffffffffu, mx1, 2));
        float nm0 = fmaxf(m0, mx0), nm1 = fmaxf(m1, mx1);
        float c0 = fast_exp(m0 - nm0), c1 = fast_exp(m1 - nm1);
        m0 = nm0; m1 = nm1;

        float rs0 = 0.f, rs1 = 0.f;
#pragma unroll
        for (int nf = 0; nf < 8; nf++) {
            float p00 = fast_exp(SC[nf][0] - m0);
            float p01 = fast_exp(SC[nf][1] - m0);
            float p10 = fast_exp(SC[nf][2] - m1);
            float p11 = fast_exp(SC[nf][3] - m1);
            rs0 += p00 + p01;
            rs1 += p10 + p11;
            QP[(rw + lg) * QP_PITCH + 8 * nf + 2 * lt]         = f2tf(p00);
            QP[(rw + lg) * QP_PITCH + 8 * nf + 2 * lt + 1]     = f2tf(p01);
            QP[(rw + lg + 8) * QP_PITCH + 8 * nf + 2 * lt]     = f2tf(p10);
            QP[(rw + lg + 8) * QP_PITCH + 8 * nf + 2 * lt + 1] = f2tf(p11);
        }
        rs0 += __shfl_xor_sync(0xffffffffu, rs0, 1);
        rs0 += __shfl_xor_sync(0xffffffffu, rs0, 2);
        rs1 += __shfl_xor_sync(0xffffffffu, rs1, 1);
        rs1 += __shfl_xor_sync(0xffffffffu, rs1, 2);
        l0 = l0 * c0 + rs0;
        l1 = l1 * c1 + rs1;
#pragma unroll
        for (int nf = 0; nf < 8; nf++) {
            OC[nf][0] *= c0; OC[nf][1] *= c0;
            OC[nf][2] *= c1; OC[nf][3] *= c1;
        }
        __syncwarp();   // P rows are warp-private

        // O += P @ V
#pragma unroll
        for (int ks = 0; ks < 8; ks++) {
            uint32_t a0 = QP[(rw + lg) * QP_PITCH + 8 * ks + lt];
            uint32_t a1 = QP[(rw + lg + 8) * QP_PITCH + 8 * ks + lt];
            uint32_t a2 = QP[(rw + lg) * QP_PITCH + 8 * ks + lt + 4];
            uint32_t a3 = QP[(rw + lg + 8) * QP_PITCH + 8 * ks + lt + 4];
#pragma unroll
            for (int nf = 0; nf < 8; nf++) {
                uint32_t b0 = Vb[(8 * ks + lt) * VS_PITCH + 8 * nf + lg];
                uint32_t b1 = Vb[(8 * ks + lt + 4) * VS_PITCH + 8 * nf + lg];
                mma_tf32(OC[nf], a0, a1, a2, a3, b0, b1);
            }
        }
        __syncthreads();  // all reads of this buffer done before it is refilled
    }

    float inv0 = 1.f / l0, inv1 = 1.f / l1;
    size_t row0 = (size_t)(b * S_ + q0 + rw + lg);
#pragma unroll
    for (int nf = 0; nf < 8; nf++) {
        int col = gh * 64 + nf * 8 + 2 * lt;
        *reinterpret_cast<float2*>(g_z + row0 * QCOLS + col) =
            make_float2(OC[nf][0] * inv0, OC[nf][1] * inv0);
        *reinterpret_cast<float2*>(g_z + (row0 + 8) * QCOLS + col) =
            make_float2(OC[nf][2] * inv1, OC[nf][3] * inv1);
    }
}

// ---------------------------------------------------------------------------
extern "C" void kernel_launch(void* const* d_in, const int* in_sizes, int n_in,
                              void* d_out, int out_size) {
    const float* x     = (const float*)d_in[0];
    const float* Wq_w  = (const float*)d_in[1];
    const float* Wq_b  = (const float*)d_in[2];
    const float* Wkv_w = (const float*)d_in[3];
    const float* Wkv_b = (const float*)d_in[4];
    const float* Wz_w  = (const float*)d_in[5];
    const float* Wz_b  = (const float*)d_in[6];
    float* out = (float*)d_out;

    cudaFuncSetAttribute(attn_mma, cudaFuncAttributeMaxDynamicSharedMemorySize,
                         ATTN_SMEM_WORDS * 4);

    float* gq;  cudaGetSymbolAddress((void**)&gq,  g_q);
    float* gkv; cudaGetSymbolAddress((void**)&gkv, g_kv);
    float* gz;  cudaGetSymbolAddress((void**)&gz,  g_z);
    float* gp;  cudaGetSymbolAddress((void**)&gp,  g_part);

    dim3 gq_grid(QCOLS / 64, M_ / 128, 1);
    gemm_tf32<<<gq_grid, 256>>>(x, Wq_w, Wq_b, gq, M_, QCOLS, D_, D_, 0);

    dim3 gkv_grid(KVCOLS / 64, M_ / 128, 1);
    gemm_tf32<<<gkv_grid, 256>>>(x, Wkv_w, Wkv_b, gkv, M_, KVCOLS, D_, D_, 0);

    dim3 ga(S_ / 128, B_ * GH_);
    attn_mma<<<ga, 256, ATTN_SMEM_WORDS * 4>>>();

    dim3 go_grid(D_ / 64, M_ / 128, KSPLIT);
    gemm_tf32<<<go_grid, 256>>>(gz, Wz_w, Wz_b, gp, M_, D_, QCOLS, QCOLS / KSPLIT, 2);

    reduce_out<<<M_ * D_ / 4 / 256, 256>>>(Wz_b, out);
}